// round 3
// baseline (speedup 1.0000x reference)
#include <cuda_runtime.h>
#include <math.h>

#define B 32
#define N 2048
#define BN (B*N)
#define QPT 4
#define TILE 512
#define CHUNKS 2   // ceil(N / (256*QPT))

// ---------------- scratch (device globals: no allocations allowed) ----------
__device__ float g_Px[BN], g_Py[BN], g_Pn[BN];   // compacted visible preds
__device__ float g_Tx[BN], g_Ty[BN], g_Tn[BN];   // compacted visible targets
__device__ int   g_cntP[B], g_cntT[B];
__device__ float g_point, g_mask, g_struct;
__device__ float g_minsum[2*B];                  // [0..B) dir P->T, [B..2B) dir T->P

// ---------------- zero accumulators (runs every graph replay) ---------------
__global__ void sk_init_kernel() {
    int t = threadIdx.x;
    if (t == 0) { g_point = 0.f; g_mask = 0.f; g_struct = 0.f; }
    if (t < 2*B) g_minsum[t] = 0.f;
}

// ---------------- elementwise losses + visibility compaction ----------------
__global__ void sk_prep_kernel(const float* __restrict__ pred,
                               const float* __restrict__ target,
                               const float* __restrict__ smask) {
    int b = blockIdx.x;
    __shared__ int sp, st;
    __shared__ float red[24];          // 8 warps x 3 sums
    if (threadIdx.x == 0) { sp = 0; st = 0; }
    __syncthreads();

    float s_point = 0.f, s_mask = 0.f, s_struct = 0.f;
    for (int n = threadIdx.x; n < N; n += blockDim.x) {
        int idx = b * N + n;
        float p0 = pred[idx*3+0],  p1 = pred[idx*3+1],  p2 = pred[idx*3+2];
        float t0 = target[idx*3+0],t1 = target[idx*3+1],t2 = target[idx*3+2];
        bool tv = (t2 == 1.0f);
        bool pv = (p2 == 1.0f);
        if (tv) {
            float d0 = p0 - t0, d1 = p1 - t1;
            s_point += d0*d0 + d1*d1;
            float m0 = smask[idx*2+0], m1 = smask[idx*2+1];
            float sm = fminf(fmaxf(m0 + m1, 0.f), 1.f);
            s_mask += sm;
            float e0 = d0 * sm, e1 = d1 * sm;
            s_struct += e0*e0 + e1*e1;
            int pos = atomicAdd(&st, 1);
            g_Tx[b*N+pos] = t0; g_Ty[b*N+pos] = t1; g_Tn[b*N+pos] = t0*t0 + t1*t1;
        }
        if (pv) {
            int pos = atomicAdd(&sp, 1);
            g_Px[b*N+pos] = p0; g_Py[b*N+pos] = p1; g_Pn[b*N+pos] = p0*p0 + p1*p1;
        }
    }

    // reduce 3 sums across the block
    #pragma unroll
    for (int o = 16; o; o >>= 1) {
        s_point  += __shfl_xor_sync(0xffffffffu, s_point,  o);
        s_mask   += __shfl_xor_sync(0xffffffffu, s_mask,   o);
        s_struct += __shfl_xor_sync(0xffffffffu, s_struct, o);
    }
    int wid = threadIdx.x >> 5, lane = threadIdx.x & 31;
    if (lane == 0) { red[wid] = s_point; red[8+wid] = s_mask; red[16+wid] = s_struct; }
    __syncthreads();
    if (threadIdx.x == 0) {
        float a = 0.f, c = 0.f, d = 0.f;
        #pragma unroll
        for (int w = 0; w < 8; w++) { a += red[w]; c += red[8+w]; d += red[16+w]; }
        atomicAdd(&g_point, a);
        atomicAdd(&g_mask, c);
        atomicAdd(&g_struct, d);
        g_cntP[b] = sp;
        g_cntT[b] = st;
    }
}

// ---------------- chamfer: min over database of d2, sum sqrt over queries ---
__global__ void __launch_bounds__(256) sk_chamfer_kernel() {
    int b = blockIdx.y, dir = blockIdx.z;
    const float *Qx, *Qy, *Qn, *Dx, *Dy, *Dn;
    int cntQ, cntD;
    if (dir == 0) {
        Qx = g_Px + b*N; Qy = g_Py + b*N; Qn = g_Pn + b*N;
        Dx = g_Tx + b*N; Dy = g_Ty + b*N; Dn = g_Tn + b*N;
        cntQ = g_cntP[b]; cntD = g_cntT[b];
    } else {
        Qx = g_Tx + b*N; Qy = g_Ty + b*N; Qn = g_Tn + b*N;
        Dx = g_Px + b*N; Dy = g_Py + b*N; Dn = g_Pn + b*N;
        cntQ = g_cntT[b]; cntD = g_cntP[b];
    }

    __shared__ float sx[TILE], sy[TILE], sn[TILE];

    int qbase = blockIdx.x * (blockDim.x * QPT);
    float px[QPT], py[QPT], pn[QPT], mm[QPT];
    bool valid[QPT];
    #pragma unroll
    for (int i = 0; i < QPT; i++) {
        int q = qbase + i * blockDim.x + threadIdx.x;
        valid[i] = (q < cntQ);
        int qa = valid[i] ? q : 0;
        px[i] = Qx[qa]; py[i] = Qy[qa]; pn[i] = Qn[qa];
        mm[i] = 3.0e38f;
    }

    for (int t0 = 0; t0 < cntD; t0 += TILE) {
        __syncthreads();
        for (int j = threadIdx.x; j < TILE; j += blockDim.x) {
            int g = t0 + j;
            if (g < cntD) {
                sx[j] = -2.0f * Dx[g];
                sy[j] = -2.0f * Dy[g];
                sn[j] = Dn[g];
            } else {
                sx[j] = 0.f; sy[j] = 0.f; sn[j] = 3.0e38f;
            }
        }
        __syncthreads();

        #pragma unroll 4
        for (int j = 0; j < TILE; j++) {
            float tx = sx[j], ty = sy[j], tn = sn[j];
            #pragma unroll
            for (int i = 0; i < QPT; i++)
                mm[i] = fminf(mm[i], fmaf(px[i], tx, fmaf(py[i], ty, tn)));
        }
    }

    float lsum = 0.f;
    #pragma unroll
    for (int i = 0; i < QPT; i++) {
        if (valid[i]) {
            float d2 = pn[i] + mm[i];
            lsum += sqrtf(fmaxf(d2, 1e-12f));
        }
    }
    #pragma unroll
    for (int o = 16; o; o >>= 1) lsum += __shfl_xor_sync(0xffffffffu, lsum, o);
    if ((threadIdx.x & 31) == 0)
        atomicAdd(&g_minsum[dir * B + b], lsum);
}

// ---------------- final combine ---------------------------------------------
__global__ void sk_final_kernel(float* __restrict__ out) {
    int t = threadIdx.x;
    float ch = 0.f;
    if (t < B) {
        float cp = (float)g_cntP[t], ct = (float)g_cntT[t];
        float mp = g_minsum[t]     / fmaxf(cp, 1.f);
        float mt = g_minsum[B + t] / fmaxf(ct, 1.f);
        ch = (cp > 0.f && ct > 0.f) ? 0.5f * (mp + mt) : 0.f;
    }
    #pragma unroll
    for (int o = 16; o; o >>= 1) ch += __shfl_xor_sync(0xffffffffu, ch, o);
    if (t == 0) {
        float lc = ch / (float)B;
        float lp = g_point / (float)(B * N * 2);
        float ls = (g_mask > 0.f) ? g_struct / (float)(B * N * 2) : 0.f;
        out[0] = lp + 5.0f * lc + 2.0f * ls;
        out[1] = lp;
        out[2] = 0.f;
        out[3] = lc;
    }
}

extern "C" void kernel_launch(void* const* d_in, const int* in_sizes, int n_in,
                              void* d_out, int out_size) {
    const float* pred   = (const float*)d_in[0];
    const float* target = (const float*)d_in[1];
    const float* smask  = (const float*)d_in[2];
    float* out = (float*)d_out;

    sk_init_kernel<<<1, 64>>>();
    sk_prep_kernel<<<B, 256>>>(pred, target, smask);
    dim3 grid(CHUNKS, B, 2);
    sk_chamfer_kernel<<<grid, 256>>>();
    sk_final_kernel<<<1, 32>>>(out);
}

// round 4
// speedup vs baseline: 1.0264x; 1.0264x over previous
#include <cuda_runtime.h>
#include <math.h>

#define B 32
#define N 2048
#define BN (B*N)

// chamfer config
#define CTHREADS 128
#define QPT 8
#define QPB (CTHREADS*QPT)       // 1024 queries per block
#define CHUNKS 2                 // N / QPB
#define TILE 512

// prep config
#define PSPLIT 4
#define PROWS (N/PSPLIT)         // 512
#define PTHREADS 256

typedef unsigned long long u64;

// ---------------- scratch (device globals; zero at module load) -------------
__device__ float g_Px[BN], g_Py[BN], g_Pn[BN];     // compacted visible preds
__device__ float g_Tx[BN], g_Ty[BN], g_Tn[BN];     // compacted visible targets
__device__ int   g_cntP[B], g_cntT[B];             // atomic counters (final zeroes them)
__device__ float g_ppart[B*PSPLIT*3];              // prep partials (unconditional writes)
__device__ float g_chsum[2*B*CHUNKS];              // chamfer partials (unconditional writes)

// ---------------- packed f32x2 helpers --------------------------------------
__device__ __forceinline__ u64 pack2(float lo, float hi) {
    u64 r; asm("mov.b64 %0,{%1,%2};" : "=l"(r) : "f"(lo), "f"(hi)); return r;
}
__device__ __forceinline__ u64 fma2(u64 a, u64 b, u64 c) {
    u64 d; asm("fma.rn.f32x2 %0,%1,%2,%3;" : "=l"(d) : "l"(a), "l"(b), "l"(c)); return d;
}
__device__ __forceinline__ void unpack2(u64 v, float& lo, float& hi) {
    asm("mov.b64 {%0,%1},%2;" : "=f"(lo), "=f"(hi) : "l"(v));
}

// ---------------- prep: elementwise losses + warp-aggregated compaction -----
__global__ void __launch_bounds__(PTHREADS) sk_prep_kernel(
        const float* __restrict__ pred,
        const float* __restrict__ target,
        const float* __restrict__ smask) {
    int s = blockIdx.x, b = blockIdx.y;
    int lane = threadIdx.x & 31, wid = threadIdx.x >> 5;
    __shared__ float red[24];   // 8 warps x 3

    float s_point = 0.f, s_mask = 0.f, s_struct = 0.f;

    #pragma unroll
    for (int it = 0; it < PROWS / PTHREADS; it++) {
        int n = s * PROWS + it * PTHREADS + threadIdx.x;
        int idx = b * N + n;
        float p0 = pred[idx*3+0],  p1 = pred[idx*3+1],  p2 = pred[idx*3+2];
        float t0 = target[idx*3+0], t1 = target[idx*3+1], t2 = target[idx*3+2];
        bool tv = (t2 == 1.0f);
        bool pv = (p2 == 1.0f);

        if (tv) {
            float d0 = p0 - t0, d1 = p1 - t1;
            s_point += d0*d0 + d1*d1;
            float m0 = smask[idx*2+0], m1 = smask[idx*2+1];
            float sm = fminf(fmaxf(m0 + m1, 0.f), 1.f);
            s_mask += sm;
            float e0 = d0 * sm, e1 = d1 * sm;
            s_struct += e0*e0 + e1*e1;
        }

        // warp-aggregated compaction: targets
        unsigned bt = __ballot_sync(0xffffffffu, tv);
        int baseT = 0;
        if (lane == 0 && bt) baseT = atomicAdd(&g_cntT[b], __popc(bt));
        baseT = __shfl_sync(0xffffffffu, baseT, 0);
        if (tv) {
            int pos = b*N + baseT + __popc(bt & ((1u << lane) - 1u));
            g_Tx[pos] = t0; g_Ty[pos] = t1; g_Tn[pos] = t0*t0 + t1*t1;
        }
        // warp-aggregated compaction: preds
        unsigned bp = __ballot_sync(0xffffffffu, pv);
        int baseP = 0;
        if (lane == 0 && bp) baseP = atomicAdd(&g_cntP[b], __popc(bp));
        baseP = __shfl_sync(0xffffffffu, baseP, 0);
        if (pv) {
            int pos = b*N + baseP + __popc(bp & ((1u << lane) - 1u));
            g_Px[pos] = p0; g_Py[pos] = p1; g_Pn[pos] = p0*p0 + p1*p1;
        }
    }

    #pragma unroll
    for (int o = 16; o; o >>= 1) {
        s_point  += __shfl_xor_sync(0xffffffffu, s_point,  o);
        s_mask   += __shfl_xor_sync(0xffffffffu, s_mask,   o);
        s_struct += __shfl_xor_sync(0xffffffffu, s_struct, o);
    }
    if (lane == 0) { red[wid] = s_point; red[8+wid] = s_mask; red[16+wid] = s_struct; }
    __syncthreads();
    if (threadIdx.x == 0) {
        float a = 0.f, c = 0.f, d = 0.f;
        #pragma unroll
        for (int w = 0; w < PTHREADS/32; w++) { a += red[w]; c += red[8+w]; d += red[16+w]; }
        int slot = (b * PSPLIT + s) * 3;
        g_ppart[slot+0] = a; g_ppart[slot+1] = c; g_ppart[slot+2] = d;
    }
}

// ---------------- chamfer: packed f32x2 min-distance ------------------------
__global__ void __launch_bounds__(CTHREADS) sk_chamfer_kernel() {
    int chunk = blockIdx.x, b = blockIdx.y, dir = blockIdx.z;
    const float *Qx, *Qy, *Qn, *Dx, *Dy, *Dn;
    int cntQ, cntD;
    if (dir == 0) {
        Qx = g_Px + b*N; Qy = g_Py + b*N; Qn = g_Pn + b*N;
        Dx = g_Tx + b*N; Dy = g_Ty + b*N; Dn = g_Tn + b*N;
        cntQ = g_cntP[b]; cntD = g_cntT[b];
    } else {
        Qx = g_Tx + b*N; Qy = g_Ty + b*N; Qn = g_Tn + b*N;
        Dx = g_Px + b*N; Dy = g_Py + b*N; Dn = g_Pn + b*N;
        cntQ = g_cntT[b]; cntD = g_cntP[b];
    }

    __shared__ u64 s2[3*TILE];   // 12 KB: {-2x,-2x}, {-2y,-2y}, {n,n}

    int qbase = chunk * QPB;
    u64 px2[QPT/2], py2[QPT/2];
    float pn[QPT], mm[QPT];
    bool valid[QPT];
    #pragma unroll
    for (int k = 0; k < QPT/2; k++) {
        int q0 = qbase + (2*k)   * CTHREADS + threadIdx.x;
        int q1 = qbase + (2*k+1) * CTHREADS + threadIdx.x;
        valid[2*k]   = (q0 < cntQ);
        valid[2*k+1] = (q1 < cntQ);
        int a0 = valid[2*k]   ? q0 : 0;
        int a1 = valid[2*k+1] ? q1 : 0;
        px2[k] = pack2(Qx[a0], Qx[a1]);
        py2[k] = pack2(Qy[a0], Qy[a1]);
        pn[2*k] = Qn[a0]; pn[2*k+1] = Qn[a1];
        mm[2*k] = 3.0e38f; mm[2*k+1] = 3.0e38f;
    }

    for (int t0 = 0; t0 < cntD; t0 += TILE) {
        __syncthreads();
        #pragma unroll
        for (int it = 0; it < TILE / CTHREADS; it++) {
            int j = it * CTHREADS + threadIdx.x;
            int g = t0 + j;
            float x, y, n2;
            if (g < cntD) { x = -2.0f*Dx[g]; y = -2.0f*Dy[g]; n2 = Dn[g]; }
            else          { x = 0.f; y = 0.f; n2 = 3.0e38f; }
            s2[j]          = pack2(x, x);
            s2[TILE + j]   = pack2(y, y);
            s2[2*TILE + j] = pack2(n2, n2);
        }
        __syncthreads();

        #pragma unroll 4
        for (int j = 0; j < TILE; j++) {
            u64 tx = s2[j], ty = s2[TILE + j], tn = s2[2*TILE + j];
            #pragma unroll
            for (int k = 0; k < QPT/2; k++) {
                u64 d = fma2(px2[k], tx, fma2(py2[k], ty, tn));
                float lo, hi; unpack2(d, lo, hi);
                mm[2*k]   = fminf(mm[2*k],   lo);
                mm[2*k+1] = fminf(mm[2*k+1], hi);
            }
        }
    }

    float lsum = 0.f;
    #pragma unroll
    for (int i = 0; i < QPT; i++)
        if (valid[i])
            lsum += sqrtf(fmaxf(pn[i] + mm[i], 1e-12f));

    #pragma unroll
    for (int o = 16; o; o >>= 1) lsum += __shfl_xor_sync(0xffffffffu, lsum, o);
    __shared__ float wred[CTHREADS/32];
    if ((threadIdx.x & 31) == 0) wred[threadIdx.x >> 5] = lsum;
    __syncthreads();
    if (threadIdx.x == 0) {
        float t = 0.f;
        #pragma unroll
        for (int w = 0; w < CTHREADS/32; w++) t += wred[w];
        g_chsum[(dir * B + b) * CHUNKS + chunk] = t;
    }
}

// ---------------- final combine + counter reset for next replay -------------
__global__ void sk_final_kernel(float* __restrict__ out) {
    int t = threadIdx.x;           // 128 threads
    __shared__ float sch[2*B];     // per (dir,b) chamfer sums
    __shared__ float scnt[2*B];    // counts
    __shared__ float sred[12];     // 4 warps x 3

    // gather prep partials (128 slots, one per thread)
    float sp = g_ppart[t*3+0], smk = g_ppart[t*3+1], sst = g_ppart[t*3+2];
    #pragma unroll
    for (int o = 16; o; o >>= 1) {
        sp  += __shfl_xor_sync(0xffffffffu, sp,  o);
        smk += __shfl_xor_sync(0xffffffffu, smk, o);
        sst += __shfl_xor_sync(0xffffffffu, sst, o);
    }
    int wid = t >> 5, lane = t & 31;
    if (lane == 0) { sred[wid] = sp; sred[4+wid] = smk; sred[8+wid] = sst; }

    // chamfer partials: t < 64 handles one (dir,b)
    if (t < 2*B) {
        float s = 0.f;
        #pragma unroll
        for (int c = 0; c < CHUNKS; c++) s += g_chsum[t*CHUNKS + c];
        sch[t] = s;
        scnt[t] = (float)((t < B) ? g_cntP[t] : g_cntT[t - B]);
    }
    __syncthreads();

    // zero atomic counters for the next graph replay
    if (t < B)            g_cntP[t] = 0;
    else if (t < 2*B)     g_cntT[t - B] = 0;

    float ch = 0.f;
    if (t < B) {
        float cp = scnt[t], ct = scnt[B + t];
        float mp = sch[t]     / fmaxf(cp, 1.f);
        float mt = sch[B + t] / fmaxf(ct, 1.f);
        ch = (cp > 0.f && ct > 0.f) ? 0.5f * (mp + mt) : 0.f;
    }
    #pragma unroll
    for (int o = 16; o; o >>= 1) ch += __shfl_xor_sync(0xffffffffu, ch, o);

    if (t == 0) {
        float a = 0.f, c = 0.f, d = 0.f;
        #pragma unroll
        for (int w = 0; w < 4; w++) { a += sred[w]; c += sred[4+w]; d += sred[8+w]; }
        float lc = ch / (float)B;
        float lp = a / (float)(B * N * 2);
        float ls = (c > 0.f) ? d / (float)(B * N * 2) : 0.f;
        out[0] = lp + 5.0f * lc + 2.0f * ls;
        out[1] = lp;
        out[2] = 0.f;
        out[3] = lc;
    }
}

extern "C" void kernel_launch(void* const* d_in, const int* in_sizes, int n_in,
                              void* d_out, int out_size) {
    const float* pred   = (const float*)d_in[0];
    const float* target = (const float*)d_in[1];
    const float* smask  = (const float*)d_in[2];
    float* out = (float*)d_out;

    dim3 pgrid(PSPLIT, B);
    sk_prep_kernel<<<pgrid, PTHREADS>>>(pred, target, smask);
    dim3 cgrid(CHUNKS, B, 2);
    sk_chamfer_kernel<<<cgrid, CTHREADS>>>();
    sk_final_kernel<<<1, 128>>>(out);
}

// round 5
// speedup vs baseline: 1.1745x; 1.1443x over previous
#include <cuda_runtime.h>
#include <math.h>

#define B 32
#define N 2048
#define BN (B*N)

// chamfer config
#define CTHREADS 128
#define QPT 8
#define QPB (CTHREADS*QPT)       // 1024 queries per block
#define QCHUNKS 2                // N / QPB
#define DCHUNKS 4
#define DTILE 512                // N / DCHUNKS

// prep config
#define PSPLIT 8
#define PROWS (N/PSPLIT)         // 256
#define PTHREADS 256

typedef unsigned long long u64;

// ---------------- scratch (device globals; zero at module load) -------------
__device__ float g_Px[BN], g_Py[BN], g_Pn[BN];     // compacted visible preds
__device__ float g_Tx[BN], g_Ty[BN], g_Tn[BN];     // compacted visible targets
__device__ int   g_cntP[B], g_cntT[B];             // atomic counters (final resets)
__device__ float g_ppart[B*PSPLIT*3];              // prep partials
__device__ unsigned g_minbits[2*BN];               // per-(dir,b,q) min d2 as bits
__device__ float g_chsum[2*B];                     // per-(dir,b) sqrt-sums
__device__ int   g_ticket;                         // final-combine ticket

// ---------------- packed f32x2 helpers --------------------------------------
__device__ __forceinline__ u64 pack2(float lo, float hi) {
    u64 r; asm("mov.b64 %0,{%1,%2};" : "=l"(r) : "f"(lo), "f"(hi)); return r;
}
__device__ __forceinline__ u64 fma2(u64 a, u64 b, u64 c) {
    u64 d; asm("fma.rn.f32x2 %0,%1,%2,%3;" : "=l"(d) : "l"(a), "l"(b), "l"(c)); return d;
}
__device__ __forceinline__ void unpack2(u64 v, float& lo, float& hi) {
    asm("mov.b64 {%0,%1},%2;" : "=f"(lo), "=f"(hi) : "l"(v));
}

// ---------------- prep: losses + compaction + min-array init ----------------
__global__ void __launch_bounds__(PTHREADS) sk_prep_kernel(
        const float* __restrict__ pred,
        const float* __restrict__ target,
        const float* __restrict__ smask) {
    int s = blockIdx.x, b = blockIdx.y;
    int lane = threadIdx.x & 31, wid = threadIdx.x >> 5;
    __shared__ float red[24];

    int n = s * PROWS + threadIdx.x;          // PROWS == PTHREADS: 1 elem/thread
    int idx = b * N + n;

    // init per-query min slots for both directions (fresh every replay)
    g_minbits[(0*B + b)*N + n] = 0x7F7FFFFFu;   // FLT_MAX bits
    g_minbits[(1*B + b)*N + n] = 0x7F7FFFFFu;

    float p0 = pred[idx*3+0],  p1 = pred[idx*3+1],  p2 = pred[idx*3+2];
    float t0 = target[idx*3+0], t1 = target[idx*3+1], t2 = target[idx*3+2];
    bool tv = (t2 == 1.0f);
    bool pv = (p2 == 1.0f);

    float s_point = 0.f, s_mask = 0.f, s_struct = 0.f;
    if (tv) {
        float d0 = p0 - t0, d1 = p1 - t1;
        s_point = d0*d0 + d1*d1;
        float m0 = smask[idx*2+0], m1 = smask[idx*2+1];
        float sm = fminf(fmaxf(m0 + m1, 0.f), 1.f);
        s_mask = sm;
        float e0 = d0 * sm, e1 = d1 * sm;
        s_struct = e0*e0 + e1*e1;
    }

    // warp-aggregated compaction
    unsigned bt = __ballot_sync(0xffffffffu, tv);
    int baseT = 0;
    if (lane == 0 && bt) baseT = atomicAdd(&g_cntT[b], __popc(bt));
    baseT = __shfl_sync(0xffffffffu, baseT, 0);
    if (tv) {
        int pos = b*N + baseT + __popc(bt & ((1u << lane) - 1u));
        g_Tx[pos] = t0; g_Ty[pos] = t1; g_Tn[pos] = t0*t0 + t1*t1;
    }
    unsigned bp = __ballot_sync(0xffffffffu, pv);
    int baseP = 0;
    if (lane == 0 && bp) baseP = atomicAdd(&g_cntP[b], __popc(bp));
    baseP = __shfl_sync(0xffffffffu, baseP, 0);
    if (pv) {
        int pos = b*N + baseP + __popc(bp & ((1u << lane) - 1u));
        g_Px[pos] = p0; g_Py[pos] = p1; g_Pn[pos] = p0*p0 + p1*p1;
    }

    #pragma unroll
    for (int o = 16; o; o >>= 1) {
        s_point  += __shfl_xor_sync(0xffffffffu, s_point,  o);
        s_mask   += __shfl_xor_sync(0xffffffffu, s_mask,   o);
        s_struct += __shfl_xor_sync(0xffffffffu, s_struct, o);
    }
    if (lane == 0) { red[wid] = s_point; red[8+wid] = s_mask; red[16+wid] = s_struct; }
    __syncthreads();
    if (threadIdx.x == 0) {
        float a = 0.f, c = 0.f, d = 0.f;
        #pragma unroll
        for (int w = 0; w < PTHREADS/32; w++) { a += red[w]; c += red[8+w]; d += red[16+w]; }
        int slot = (b * PSPLIT + s) * 3;
        g_ppart[slot+0] = a; g_ppart[slot+1] = c; g_ppart[slot+2] = d;
    }
}

// ---------------- chamfer: D-split, packed f32x2, atomicMin merge -----------
__global__ void __launch_bounds__(CTHREADS) sk_chamfer_kernel() {
    int qchunk = blockIdx.x, b = blockIdx.y;
    int dir = blockIdx.z >> 2, dchunk = blockIdx.z & 3;

    const float *Qx, *Qy, *Qn, *Dx, *Dy, *Dn;
    int cntQ, cntD;
    if (dir == 0) {
        Qx = g_Px + b*N; Qy = g_Py + b*N; Qn = g_Pn + b*N;
        Dx = g_Tx + b*N; Dy = g_Ty + b*N; Dn = g_Tn + b*N;
        cntQ = g_cntP[b]; cntD = g_cntT[b];
    } else {
        Qx = g_Tx + b*N; Qy = g_Ty + b*N; Qn = g_Tn + b*N;
        Dx = g_Px + b*N; Dy = g_Py + b*N; Dn = g_Pn + b*N;
        cntQ = g_cntT[b]; cntD = g_cntP[b];
    }

    int dstart = dchunk * DTILE;
    if (dstart >= cntD) return;           // other chunks cover the min
    int dlen = min(DTILE, cntD - dstart);

    __shared__ u64 s2[3*DTILE];           // 12 KB duplicated {-2x}, {-2y}, {n}

    #pragma unroll
    for (int it = 0; it < DTILE / CTHREADS; it++) {
        int j = it * CTHREADS + threadIdx.x;
        float x, y, n2;
        if (j < dlen) {
            int g = dstart + j;
            x = -2.0f*Dx[g]; y = -2.0f*Dy[g]; n2 = Dn[g];
        } else { x = 0.f; y = 0.f; n2 = 3.0e38f; }
        s2[j]           = pack2(x, x);
        s2[DTILE + j]   = pack2(y, y);
        s2[2*DTILE + j] = pack2(n2, n2);
    }

    int qbase = qchunk * QPB;
    u64 px2[QPT/2], py2[QPT/2];
    float pn[QPT], mm[QPT];
    bool valid[QPT];
    #pragma unroll
    for (int k = 0; k < QPT/2; k++) {
        int q0 = qbase + (2*k)   * CTHREADS + threadIdx.x;
        int q1 = qbase + (2*k+1) * CTHREADS + threadIdx.x;
        valid[2*k]   = (q0 < cntQ);
        valid[2*k+1] = (q1 < cntQ);
        int a0 = valid[2*k]   ? q0 : 0;
        int a1 = valid[2*k+1] ? q1 : 0;
        px2[k] = pack2(Qx[a0], Qx[a1]);
        py2[k] = pack2(Qy[a0], Qy[a1]);
        pn[2*k] = Qn[a0]; pn[2*k+1] = Qn[a1];
        mm[2*k] = 3.0e38f; mm[2*k+1] = 3.0e38f;
    }
    __syncthreads();

    #pragma unroll 4
    for (int j = 0; j < DTILE; j++) {
        u64 tx = s2[j], ty = s2[DTILE + j], tn = s2[2*DTILE + j];
        #pragma unroll
        for (int k = 0; k < QPT/2; k++) {
            u64 d = fma2(px2[k], tx, fma2(py2[k], ty, tn));
            float lo, hi; unpack2(d, lo, hi);
            mm[2*k]   = fminf(mm[2*k],   lo);
            mm[2*k+1] = fminf(mm[2*k+1], hi);
        }
    }

    unsigned* minb = g_minbits + (dir*B + b)*N;
    #pragma unroll
    for (int i = 0; i < QPT; i++) {
        if (valid[i]) {
            int q = qbase + i * CTHREADS + threadIdx.x;
            float v = fmaxf(pn[i] + mm[i], 1e-12f);   // clamp: keep bits monotone
            atomicMin(&minb[q], __float_as_uint(v));
        }
    }
}

// ---------------- final: per-(dir,b) sqrt-sum, last block combines ----------
__global__ void __launch_bounds__(256) sk_final_kernel(float* __restrict__ out) {
    int db = blockIdx.x;                  // 0..63 = dir*B + b
    int t = threadIdx.x;
    int dir = db >> 5, b = db & 31;
    int cnt = (dir == 0) ? g_cntP[b] : g_cntT[b];

    __shared__ float wred[8];
    __shared__ int s_ticket;

    const unsigned* minb = g_minbits + db * N;
    float s = 0.f;
    #pragma unroll
    for (int it = 0; it < N / 256; it++) {
        int q = it * 256 + t;
        if (q < cnt) s += sqrtf(__uint_as_float(minb[q]));
    }
    #pragma unroll
    for (int o = 16; o; o >>= 1) s += __shfl_xor_sync(0xffffffffu, s, o);
    if ((t & 31) == 0) wred[t >> 5] = s;
    __syncthreads();
    if (t == 0) {
        float tot = 0.f;
        #pragma unroll
        for (int w = 0; w < 8; w++) tot += wred[w];
        g_chsum[db] = tot;
        __threadfence();
        s_ticket = atomicAdd(&g_ticket, 1);
    }
    __syncthreads();
    if (s_ticket != 2*B - 1) return;      // only the last-finishing block combines
    __threadfence();

    // ---- combine (one block, 256 threads) ----
    __shared__ float sch[2*B], scnt[2*B], sred[24];
    volatile float* vch = g_chsum;
    if (t < 2*B) {
        sch[t]  = vch[t];
        scnt[t] = (float)((t < B) ? g_cntP[t] : g_cntT[t - B]);
    }
    // prep partials: 256 slots, one per thread
    float sp = g_ppart[t*3+0], smk = g_ppart[t*3+1], sst = g_ppart[t*3+2];
    #pragma unroll
    for (int o = 16; o; o >>= 1) {
        sp  += __shfl_xor_sync(0xffffffffu, sp,  o);
        smk += __shfl_xor_sync(0xffffffffu, smk, o);
        sst += __shfl_xor_sync(0xffffffffu, sst, o);
    }
    if ((t & 31) == 0) { int w = t >> 5; sred[w] = sp; sred[8+w] = smk; sred[16+w] = sst; }
    __syncthreads();

    // reset state for next graph replay (counts already snapshotted in scnt)
    if (t < B)        g_cntP[t] = 0;
    else if (t < 2*B) g_cntT[t - B] = 0;
    if (t == 0)       g_ticket = 0;

    float ch = 0.f;
    if (t < B) {
        float cp = scnt[t], ct = scnt[B + t];
        float mp = sch[B + t] / fmaxf(cp, 1.f);   // dir1: T->P uses cntT? no:
        // dir0 (db<32): queries=preds  -> sum over preds,   divide by cntP
        // dir1 (db>=32): queries=targets -> sum over targets, divide by cntT
        mp = sch[t]     / fmaxf(cp, 1.f);
        float mt = sch[B + t] / fmaxf(ct, 1.f);
        ch = (cp > 0.f && ct > 0.f) ? 0.5f * (mp + mt) : 0.f;
    }
    #pragma unroll
    for (int o = 16; o; o >>= 1) ch += __shfl_xor_sync(0xffffffffu, ch, o);

    if (t == 0) {
        float a = 0.f, c = 0.f, d = 0.f;
        #pragma unroll
        for (int w = 0; w < 8; w++) { a += sred[w]; c += sred[8+w]; d += sred[16+w]; }
        float lc = ch / (float)B;
        float lp = a / (float)(B * N * 2);
        float ls = (c > 0.f) ? d / (float)(B * N * 2) : 0.f;
        out[0] = lp + 5.0f * lc + 2.0f * ls;
        out[1] = lp;
        out[2] = 0.f;
        out[3] = lc;
    }
}

extern "C" void kernel_launch(void* const* d_in, const int* in_sizes, int n_in,
                              void* d_out, int out_size) {
    const float* pred   = (const float*)d_in[0];
    const float* target = (const float*)d_in[1];
    const float* smask  = (const float*)d_in[2];
    float* out = (float*)d_out;

    dim3 pgrid(PSPLIT, B);
    sk_prep_kernel<<<pgrid, PTHREADS>>>(pred, target, smask);
    dim3 cgrid(QCHUNKS, B, 2 * DCHUNKS);
    sk_chamfer_kernel<<<cgrid, CTHREADS>>>();
    sk_final_kernel<<<2*B, 256>>>(out);
}